// round 13
// baseline (speedup 1.0000x reference)
#include <cuda_runtime.h>
#include <cstdint>

// out = u2 + trilinear(u1, grid + u2), [B=2,160,160,160,3] fp32.
// All global traffic through cp.async.bulk (TMA engine): w1 tile + u2 subtile
// in via one mbarrier; results staged in smem and bulk-stored out.
// Two blocks co-reside per SM.

#define Dd 160
#define Hh 160
#define Ww 160
#define HW  (Hh * Ww)
#define DHW (Dd * HW)

#define TX 10
#define TY 10
#define TZ 16
#define HALO 4
#define SX (TX + 2 * HALO)   // 18
#define SY (TY + 2 * HALO)   // 18
#define SZ (TZ + 2 * HALO)   // 24
#define RS (SZ * 3)          // 72 floats per tile row (== 8 mod 32)
#define NROW (SX * SY)       // 324
#define BUF (NROW * RS)      // 23328 floats = 93,312 B
#define UROW (TZ * 3)        // 48 floats per u2/out row
#define NXY (TX * TY)        // 100 u2 rows
#define NU2 (NXY * UROW)     // 4800 floats = 19,200 B
#define TPB 512
#define NWARP (TPB / 32)     // 16
#define NTASK ((TX / 2) * TY)// 50 warp tasks: (x-pair, y)

#define MAGIC 12582912.0f    // 1.5 * 2^23
#define MAGIC_I 0x4B400000

extern __shared__ float s[];   // [BUF tile][NU2 u2/out staging][mbarrier]

__device__ __forceinline__ void fast_floor(float v, int& i, float& f)
{
    const float fm = (v - 0.5f) + MAGIC;
    i = __float_as_int(fm) - MAGIC_I;
    f = fm - MAGIC;
}

__global__ __launch_bounds__(TPB, 2)
void compose_tma_kernel(const float* __restrict__ w1,
                        const float* __restrict__ w2,
                        float* __restrict__ out)
{
    float* __restrict__ su = s + BUF;        // u2 / result staging

    const int xt = blockIdx.x & 15;          // 0..15
    const int yt = blockIdx.x >> 4;          // 0..15
    const int x0 = xt * TX;
    const int y0 = yt * TY;
    const int z0 = blockIdx.y * TZ;
    const int b  = blockIdx.z;

    const int t    = threadIdx.x;
    const int lane = t & 31;
    const int wrp  = t >> 5;

    const float* __restrict__ w1b = w1 + (size_t)b * (size_t)DHW * 3;

    const uint32_t mbar  = (uint32_t)__cvta_generic_to_shared(s + BUF + NU2);
    const uint32_t sbase = (uint32_t)__cvta_generic_to_shared(s);
    const uint32_t ubase = (uint32_t)__cvta_generic_to_shared(su);

    // tile z-range (contiguous per row, 16B aligned both sides)
    const int zlo    = (z0 == 0) ? 0 : z0 - HALO;
    const int zhi    = (z0 + TZ + HALO > Ww) ? Ww : z0 + TZ + HALO;
    const int nbytes = (zhi - zlo) * 12;            // 288 or 240
    const int dstob  = (zlo - (z0 - HALO)) * 12;    // 0 or 48 bytes

    // valid tile rows for expect_tx
    const int xlo = (x0 - HALO < 0) ? 0 : x0 - HALO;
    const int xhi = (x0 + TX + HALO > Dd) ? Dd : x0 + TX + HALO;
    const int ylo = (y0 - HALO < 0) ? 0 : y0 - HALO;
    const int yhi = (y0 + TY + HALO > Hh) ? Hh : y0 + TY + HALO;
    const unsigned total_tx =
        (unsigned)((xhi - xlo) * (yhi - ylo) * nbytes) + NXY * UROW * 4;

    if (t == 0) {
        asm volatile("mbarrier.init.shared.b64 [%0], 1;"
                     :: "r"(mbar) : "memory");
    }
    __syncthreads();
    if (t == 0) {
        asm volatile("mbarrier.arrive.expect_tx.shared.b64 _, [%0], %1;"
                     :: "r"(mbar), "r"(total_tx) : "memory");
    }

    // ---- w1 tile fill: one 288B/240B bulk copy per (x,y) row ----
    if (t < NROW) {
        const int hx = t / SY;
        const int hy = t - hx * SY;
        const int cx = x0 - HALO + hx;
        const int cy = y0 - HALO + hy;
        if ((unsigned)cx < (unsigned)Dd && (unsigned)cy < (unsigned)Hh) {
            const float* src = w1b + (size_t)(cx * Hh + cy) * (Ww * 3) + zlo * 3;
            asm volatile(
                "cp.async.bulk.shared::cta.global.mbarrier::complete_tx::bytes "
                "[%0], [%1], %2, [%3];"
                :: "r"(sbase + t * (RS * 4) + dstob), "l"(src), "r"(nbytes),
                   "r"(mbar) : "memory");
        }
    }
    // ---- u2 subtile fill: 100 rows x 192B ----
    if (t < NXY) {
        const int xi = t / TY;
        const int yi = t - xi * TY;
        const float* src = w2 +
            ((size_t)((b * Dd + x0 + xi) * Hh + y0 + yi) * Ww + z0) * 3;
        asm volatile(
            "cp.async.bulk.shared::cta.global.mbarrier::complete_tx::bytes "
            "[%0], [%1], %2, [%3];"
            :: "r"(ubase + t * (UROW * 4)), "l"(src), "r"(UROW * 4),
               "r"(mbar) : "memory");
    }

    // ---- Compute mapping: lane = (xsub, z16); warp task = (x-pair, y) ----
    const int xsub = lane >> 4;
    const int hz   = lane & 15;
    const int z    = z0 + hz;

    // Wait for all bulk copies (acquire).
    {
        uint32_t done;
        asm volatile(
            "{\n\t.reg .pred p;\n\t"
            "mbarrier.try_wait.parity.acquire.cta.shared::cta.b64 p, [%1], 0;\n\t"
            "selp.b32 %0, 1, 0, p;\n\t}"
            : "=r"(done) : "r"(mbar) : "memory");
        while (!done) {
            asm volatile(
                "{\n\t.reg .pred p;\n\t"
                "mbarrier.try_wait.parity.acquire.cta.shared::cta.b64 p, [%1], 0, 0x989680;\n\t"
                "selp.b32 %0, 1, 0, p;\n\t}"
                : "=r"(done) : "r"(mbar) : "memory");
        }
    }

    for (int task = wrp; task < NTASK; task += NWARP) {
        const int xp = task / 10;
        const int xi = xp * 2 + xsub;
        const int yi = task - xp * 10;
        const int x  = x0 + xi;
        const int y  = y0 + yi;

        float* __restrict__ uslot = su + (xi * TY + yi) * UROW + hz * 3;
        const float u2x = uslot[0];
        const float u2y = uslot[1];
        const float u2z = uslot[2];

        const float lx = fminf(fmaxf((float)x + u2x, 0.0f), (float)(Dd - 1));
        const float ly = fminf(fmaxf((float)y + u2y, 0.0f), (float)(Hh - 1));
        const float lz = fminf(fmaxf((float)z + u2z, 0.0f), (float)(Ww - 1));

        int ix0, iy0, iz0;
        float fx, fy, fz;
        fast_floor(lx, ix0, fx);
        fast_floor(ly, iy0, fy);
        fast_floor(lz, iz0, fz);
        const float wx = lx - fx, wy = ly - fy, wz = lz - fz;
        const float wx0 = 1.0f - wx, wy0 = 1.0f - wy, wz0 = 1.0f - wz;

        const int sx0 = ix0 - (x0 - HALO);
        const int sy0 = iy0 - (y0 - HALO);
        const int sz0 = iz0 - (z0 - HALO);

        float ox, oy, oz;

        const bool fast = ((unsigned)sx0 <= (unsigned)(SX - 2)) &&
                          ((unsigned)sy0 <= (unsigned)(SY - 2)) &&
                          ((unsigned)sz0 <= (unsigned)(SZ - 2));
        if (fast) {
            const int za = sz0 * 3;
            const int zb = za + 3;

            const float* p00 = s + (sx0 * SY + sy0) * RS;
            const float* p01 = p00 + RS;
            const float* p10 = p00 + SY * RS;
            const float* p11 = p10 + RS;

            float acc[3];
#pragma unroll
            for (int c = 0; c < 3; ++c) {
                const float v00 = p00[za + c] * wz0 + p00[zb + c] * wz;
                const float v01 = p01[za + c] * wz0 + p01[zb + c] * wz;
                const float v10 = p10[za + c] * wz0 + p10[zb + c] * wz;
                const float v11 = p11[za + c] * wz0 + p11[zb + c] * wz;
                acc[c] = (v00 * wy0 + v01 * wy) * wx0 +
                         (v10 * wy0 + v11 * wy) * wx;
            }
            ox = acc[0]; oy = acc[1]; oz = acc[2];
        } else {
            // Rare slow path (~0.02% of threads): direct global gather.
            const int ix1 = min(ix0 + 1, Dd - 1);
            const int iy1 = min(iy0 + 1, Hh - 1);
            const int iz1 = min(iz0 + 1, Ww - 1);
            float a0 = 0.f, a1 = 0.f, a2 = 0.f;
#pragma unroll
            for (int cx = 0; cx < 2; ++cx) {
                const int   ix  = cx ? ix1 : ix0;
                const float wxx = cx ? wx : wx0;
#pragma unroll
                for (int cy = 0; cy < 2; ++cy) {
                    const int   iy  = cy ? iy1 : iy0;
                    const float wxy = wxx * (cy ? wy : wy0);
#pragma unroll
                    for (int cz = 0; cz < 2; ++cz) {
                        const int   iz  = cz ? iz1 : iz0;
                        const float wgt = wxy * (cz ? wz : wz0);
                        const int off = ((ix * Hh + iy) * Ww + iz) * 3;
                        a0 = fmaf(__ldg(w1b + off + 0), wgt, a0);
                        a1 = fmaf(__ldg(w1b + off + 1), wgt, a1);
                        a2 = fmaf(__ldg(w1b + off + 2), wgt, a2);
                    }
                }
            }
            ox = a0; oy = a1; oz = a2;
        }

        // In-place: this thread exclusively owns these 3 staging slots.
        uslot[0] = u2x + ox;
        uslot[1] = u2y + oy;
        uslot[2] = u2z + oz;
    }

    __syncthreads();
    asm volatile("fence.proxy.async.shared::cta;" ::: "memory");

    // ---- Bulk store: staging -> out, one 192B row per thread ----
    if (t < NXY) {
        const int xi = t / TY;
        const int yi = t - xi * TY;
        float* dst = out +
            ((size_t)((b * Dd + x0 + xi) * Hh + y0 + yi) * Ww + z0) * 3;
        asm volatile(
            "cp.async.bulk.global.shared::cta.bulk_group [%0], [%1], %2;"
            :: "l"(dst), "r"(ubase + t * (UROW * 4)), "r"(UROW * 4)
            : "memory");
        asm volatile("cp.async.bulk.commit_group;" ::: "memory");
        asm volatile("cp.async.bulk.wait_group.read 0;" ::: "memory");
    }
}

extern "C" void kernel_launch(void* const* d_in, const int* in_sizes, int n_in,
                              void* d_out, int out_size)
{
    const float* warp1 = (const float*)d_in[0];
    const float* warp2 = (const float*)d_in[1];
    float* out = (float*)d_out;

    static const size_t smem_bytes = (BUF + NU2) * sizeof(float) + 16; // 112,528
    cudaFuncSetAttribute(compose_tma_kernel,
                         cudaFuncAttributeMaxDynamicSharedMemorySize,
                         (int)smem_bytes);

    dim3 grid(256, Ww / TZ, 2);   // 5120 blocks
    compose_tma_kernel<<<grid, TPB, smem_bytes>>>(warp1, warp2, out);
}

// round 14
// speedup vs baseline: 1.3625x; 1.3625x over previous
#include <cuda_runtime.h>
#include <cuda.h>
#include <cstdint>

// out = u2 + trilinear(u1, grid + u2), [B=2,160,160,160,3] fp32.
// R12 structure (x-paired warps, magic floor, u2 LDG prefetch, __stcs out),
// tile filled by ONE 3D tensor-map TMA load (box 72x18x18 floats) when the
// driver entry point is available; otherwise per-row cp.async.bulk (R12).
// Two blocks co-reside per SM.

#define Dd 160
#define Hh 160
#define Ww 160
#define HW  (Hh * Ww)
#define DHW (Dd * HW)

#define TX 10
#define TY 10
#define TZ 16
#define HALO 4
#define SX (TX + 2 * HALO)   // 18
#define SY (TY + 2 * HALO)   // 18
#define SZ (TZ + 2 * HALO)   // 24
#define RS (SZ * 3)          // 72 floats per tile row (== 8 mod 32)
#define NROW (SX * SY)       // 324
#define BUF (NROW * RS)      // 23328 floats = 93,312 B
#define TPB 512
#define NWARP (TPB / 32)     // 16
#define NTASK ((TX / 2) * TY)// 50 warp tasks: (x-pair, y)

#define MAGIC 12582912.0f    // 1.5 * 2^23
#define MAGIC_I 0x4B400000

extern __shared__ float s[];   // [BUF floats][mbarrier]

__device__ __forceinline__ void fast_floor(float v, int& i, float& f)
{
    const float fm = (v - 0.5f) + MAGIC;
    i = __float_as_int(fm) - MAGIC_I;
    f = fm - MAGIC;
}

template <bool USE_TMAP>
__global__ __launch_bounds__(TPB, 2)
void compose_kernel(const __grid_constant__ CUtensorMap tmap,
                    const float* __restrict__ w1,
                    const float* __restrict__ w2,
                    float* __restrict__ out)
{
    const int xt = blockIdx.x & 15;          // 0..15
    const int yt = blockIdx.x >> 4;          // 0..15
    const int x0 = xt * TX;
    const int y0 = yt * TY;
    const int z0 = blockIdx.y * TZ;
    const int b  = blockIdx.z;

    const int t    = threadIdx.x;
    const int lane = t & 31;
    const int wrp  = t >> 5;

    const float* __restrict__ w1b = w1 + (size_t)b * (size_t)DHW * 3;

    const uint32_t mbar  = (uint32_t)__cvta_generic_to_shared(s + BUF);
    const uint32_t sbase = (uint32_t)__cvta_generic_to_shared(s);

    if (t == 0) {
        asm volatile("mbarrier.init.shared.b64 [%0], 1;"
                     :: "r"(mbar) : "memory");
    }
    __syncthreads();

    if (USE_TMAP) {
        // ---- One 3D TMA tensor load: box (72 fl, 18, 18), OOB zero-fill ----
        if (t == 0) {
            asm volatile("mbarrier.arrive.expect_tx.shared.b64 _, [%0], %1;"
                         :: "r"(mbar), "n"(BUF * 4) : "memory");
            const int c0 = (z0 - HALO) * 3;
            const int c1 = y0 - HALO;
            const int c2 = b * Dd + x0 - HALO;
            asm volatile(
                "cp.async.bulk.tensor.3d.shared::cta.global.tile."
                "mbarrier::complete_tx::bytes [%0], [%1, {%2, %3, %4}], [%5];"
                :: "r"(sbase), "l"(&tmap), "r"(c0), "r"(c1), "r"(c2),
                   "r"(mbar) : "memory");
        }
    } else {
        // ---- Fallback: one 288B/240B bulk copy per (x,y) row (R12) ----
        const int zlo    = (z0 == 0) ? 0 : z0 - HALO;
        const int zhi    = (z0 + TZ + HALO > Ww) ? Ww : z0 + TZ + HALO;
        const int nbytes = (zhi - zlo) * 12;
        const int dstob  = (zlo - (z0 - HALO)) * 12;
        const int xlo = (x0 - HALO < 0) ? 0 : x0 - HALO;
        const int xhi = (x0 + TX + HALO > Dd) ? Dd : x0 + TX + HALO;
        const int ylo = (y0 - HALO < 0) ? 0 : y0 - HALO;
        const int yhi = (y0 + TY + HALO > Hh) ? Hh : y0 + TY + HALO;
        if (t == 0) {
            const unsigned total_tx =
                (unsigned)((xhi - xlo) * (yhi - ylo) * nbytes);
            asm volatile("mbarrier.arrive.expect_tx.shared.b64 _, [%0], %1;"
                         :: "r"(mbar), "r"(total_tx) : "memory");
        }
        __syncthreads();
        if (t < NROW) {
            const int hx = t / SY;
            const int hy = t - hx * SY;
            const int cx = x0 - HALO + hx;
            const int cy = y0 - HALO + hy;
            if ((unsigned)cx < (unsigned)Dd && (unsigned)cy < (unsigned)Hh) {
                const float* src =
                    w1b + (size_t)(cx * Hh + cy) * (Ww * 3) + zlo * 3;
                asm volatile(
                    "cp.async.bulk.shared::cta.global."
                    "mbarrier::complete_tx::bytes [%0], [%1], %2, [%3];"
                    :: "r"(sbase + t * (RS * 4) + dstob), "l"(src),
                       "r"(nbytes), "r"(mbar) : "memory");
            }
        }
    }

    // ---- Compute mapping: lane = (xsub, z16); warp task = (x-pair, y) ----
    const int xsub = lane >> 4;
    const int hz   = lane & 15;
    const int z    = z0 + hz;

    // Prefetch first task's u2 while the TMA is in flight.
    int task = wrp;
    int nf;
    float nux, nuy, nuz;
    {
        const int xp = task / 10, yi = task - xp * 10;
        nf  = (((b * Dd + x0 + xp * 2 + xsub) * Hh + y0 + yi) * Ww + z) * 3;
        nux = __ldg(w2 + nf + 0);
        nuy = __ldg(w2 + nf + 1);
        nuz = __ldg(w2 + nf + 2);
    }

    // Wait for tile completion (acquire).
    {
        uint32_t done;
        asm volatile(
            "{\n\t.reg .pred p;\n\t"
            "mbarrier.try_wait.parity.acquire.cta.shared::cta.b64 p, [%1], 0;\n\t"
            "selp.b32 %0, 1, 0, p;\n\t}"
            : "=r"(done) : "r"(mbar) : "memory");
        while (!done) {
            asm volatile(
                "{\n\t.reg .pred p;\n\t"
                "mbarrier.try_wait.parity.acquire.cta.shared::cta.b64 p, [%1], 0, 0x989680;\n\t"
                "selp.b32 %0, 1, 0, p;\n\t}"
                : "=r"(done) : "r"(mbar) : "memory");
        }
    }

    for (; task < NTASK; task += NWARP) {
        const int xp = task / 10;
        const int x  = x0 + xp * 2 + xsub;
        const int y  = y0 + (task - xp * 10);
        const int f  = nf;
        const float u2x = nux, u2y = nuy, u2z = nuz;

        if (task + NWARP < NTASK) {      // prefetch next task's u2
            const int nt  = task + NWARP;
            const int xp2 = nt / 10;
            nf  = (((b * Dd + x0 + xp2 * 2 + xsub) * Hh +
                    y0 + (nt - xp2 * 10)) * Ww + z) * 3;
            nux = __ldg(w2 + nf + 0);
            nuy = __ldg(w2 + nf + 1);
            nuz = __ldg(w2 + nf + 2);
        }

        const float lx = fminf(fmaxf((float)x + u2x, 0.0f), (float)(Dd - 1));
        const float ly = fminf(fmaxf((float)y + u2y, 0.0f), (float)(Hh - 1));
        const float lz = fminf(fmaxf((float)z + u2z, 0.0f), (float)(Ww - 1));

        int ix0, iy0, iz0;
        float fx, fy, fz;
        fast_floor(lx, ix0, fx);
        fast_floor(ly, iy0, fy);
        fast_floor(lz, iz0, fz);
        const float wx = lx - fx, wy = ly - fy, wz = lz - fz;
        const float wx0 = 1.0f - wx, wy0 = 1.0f - wy, wz0 = 1.0f - wz;

        const int sx0 = ix0 - (x0 - HALO);
        const int sy0 = iy0 - (y0 - HALO);
        const int sz0 = iz0 - (z0 - HALO);

        float ox, oy, oz;

        const bool fast = ((unsigned)sx0 <= (unsigned)(SX - 2)) &&
                          ((unsigned)sy0 <= (unsigned)(SY - 2)) &&
                          ((unsigned)sz0 <= (unsigned)(SZ - 2));
        if (fast) {
            const int za = sz0 * 3;
            const int zb = za + 3;

            const float* p00 = s + (sx0 * SY + sy0) * RS;
            const float* p01 = p00 + RS;
            const float* p10 = p00 + SY * RS;
            const float* p11 = p10 + RS;

            float acc[3];
#pragma unroll
            for (int c = 0; c < 3; ++c) {
                const float v00 = p00[za + c] * wz0 + p00[zb + c] * wz;
                const float v01 = p01[za + c] * wz0 + p01[zb + c] * wz;
                const float v10 = p10[za + c] * wz0 + p10[zb + c] * wz;
                const float v11 = p11[za + c] * wz0 + p11[zb + c] * wz;
                acc[c] = (v00 * wy0 + v01 * wy) * wx0 +
                         (v10 * wy0 + v11 * wy) * wx;
            }
            ox = acc[0]; oy = acc[1]; oz = acc[2];
        } else {
            // Rare slow path (~0.02% of threads): direct global gather.
            const int ix1 = min(ix0 + 1, Dd - 1);
            const int iy1 = min(iy0 + 1, Hh - 1);
            const int iz1 = min(iz0 + 1, Ww - 1);
            float a0 = 0.f, a1 = 0.f, a2 = 0.f;
#pragma unroll
            for (int cx = 0; cx < 2; ++cx) {
                const int   ix  = cx ? ix1 : ix0;
                const float wxx = cx ? wx : wx0;
#pragma unroll
                for (int cy = 0; cy < 2; ++cy) {
                    const int   iy  = cy ? iy1 : iy0;
                    const float wxy = wxx * (cy ? wy : wy0);
#pragma unroll
                    for (int cz = 0; cz < 2; ++cz) {
                        const int   iz  = cz ? iz1 : iz0;
                        const float wgt = wxy * (cz ? wz : wz0);
                        const int off = ((ix * Hh + iy) * Ww + iz) * 3;
                        a0 = fmaf(__ldg(w1b + off + 0), wgt, a0);
                        a1 = fmaf(__ldg(w1b + off + 1), wgt, a1);
                        a2 = fmaf(__ldg(w1b + off + 2), wgt, a2);
                    }
                }
            }
            ox = a0; oy = a1; oz = a2;
        }

        __stcs(out + f + 0, u2x + ox);
        __stcs(out + f + 1, u2y + oy);
        __stcs(out + f + 2, u2z + oz);
    }
}

typedef CUresult (*EncodeFn)(
    CUtensorMap*, CUtensorMapDataType, cuuint32_t, void*,
    const cuuint64_t*, const cuuint64_t*, const cuuint32_t*, const cuuint32_t*,
    CUtensorMapInterleave, CUtensorMapSwizzle, CUtensorMapL2promotion,
    CUtensorMapFloatOOBfill);

extern "C" void kernel_launch(void* const* d_in, const int* in_sizes, int n_in,
                              void* d_out, int out_size)
{
    const float* warp1 = (const float*)d_in[0];
    const float* warp2 = (const float*)d_in[1];
    float* out = (float*)d_out;

    const size_t smem_bytes = BUF * sizeof(float) + 16;  // 93,328

    // Try to build the 3D tensor map (cudart-only driver entry lookup).
    CUtensorMap tmap;
    bool have_tmap = false;
    {
        void* fn = nullptr;
        cudaDriverEntryPointQueryResult qr =
            cudaDriverEntryPointSymbolNotFound;
        cudaError_t e = cudaGetDriverEntryPoint(
            "cuTensorMapEncodeTiled", &fn, cudaEnableDefault, &qr);
        if (e == cudaSuccess && fn != nullptr &&
            qr == cudaDriverEntryPointSuccess) {
            cuuint64_t dims[3]    = {Ww * 3, Hh, (cuuint64_t)(2 * Dd)};
            cuuint64_t strides[2] = {Ww * 3 * 4, (cuuint64_t)Hh * Ww * 3 * 4};
            cuuint32_t box[3]     = {RS, SY, SX};
            cuuint32_t es[3]      = {1, 1, 1};
            EncodeFn enc = (EncodeFn)fn;
            CUresult r = enc(&tmap, CU_TENSOR_MAP_DATA_TYPE_FLOAT32, 3,
                             (void*)warp1, dims, strides, box, es,
                             CU_TENSOR_MAP_INTERLEAVE_NONE,
                             CU_TENSOR_MAP_SWIZZLE_NONE,
                             CU_TENSOR_MAP_L2_PROMOTION_L2_128B,
                             CU_TENSOR_MAP_FLOAT_OOB_FILL_NONE);
            have_tmap = (r == CUDA_SUCCESS);
        }
    }
    if (!have_tmap) {
        __builtin_memset(&tmap, 0, sizeof(tmap));  // unused by fallback
    }

    dim3 grid(256, Ww / TZ, 2);   // 5120 blocks

    if (have_tmap) {
        cudaFuncSetAttribute(compose_kernel<true>,
                             cudaFuncAttributeMaxDynamicSharedMemorySize,
                             (int)smem_bytes);
        compose_kernel<true><<<grid, TPB, smem_bytes>>>(tmap, warp1, warp2, out);
    } else {
        cudaFuncSetAttribute(compose_kernel<false>,
                             cudaFuncAttributeMaxDynamicSharedMemorySize,
                             (int)smem_bytes);
        compose_kernel<false><<<grid, TPB, smem_bytes>>>(tmap, warp1, warp2, out);
    }
}

// round 15
// speedup vs baseline: 1.4561x; 1.0687x over previous
#include <cuda_runtime.h>
#include <cuda.h>
#include <cstdint>

// out = u2 + trilinear(u1, grid + u2), [B=2,160,160,160,3] fp32.
// R14 structure; tile enlarged to 16x8x16 (+halo 4) => less halo redundancy,
// NTASK=64 = exactly 4 rounds per warp, pure-shift task decode.
// Tile filled by ONE 3D tensor-map TMA load; per-row bulk-copy fallback.
// Two blocks co-reside per SM.

#define Dd 160
#define Hh 160
#define Ww 160
#define HW  (Hh * Ww)
#define DHW (Dd * HW)

#define TX 16
#define TY 8
#define TZ 16
#define HALO 4
#define SX (TX + 2 * HALO)   // 24
#define SY (TY + 2 * HALO)   // 16
#define SZ (TZ + 2 * HALO)   // 24
#define RS (SZ * 3)          // 72 floats per tile row (== 8 mod 32)
#define NROW (SX * SY)       // 384
#define BUF (NROW * RS)      // 27648 floats = 110,592 B
#define TPB 512
#define NWARP (TPB / 32)     // 16
#define NTASK ((TX / 2) * TY)// 64 warp tasks: (x-pair, y), 4 rounds exactly

#define MAGIC 12582912.0f    // 1.5 * 2^23
#define MAGIC_I 0x4B400000

extern __shared__ float s[];   // [BUF floats][mbarrier]

__device__ __forceinline__ void fast_floor(float v, int& i, float& f)
{
    const float fm = (v - 0.5f) + MAGIC;
    i = __float_as_int(fm) - MAGIC_I;
    f = fm - MAGIC;
}

template <bool USE_TMAP>
__global__ __launch_bounds__(TPB, 2)
void compose_kernel(const __grid_constant__ CUtensorMap tmap,
                    const float* __restrict__ w1,
                    const float* __restrict__ w2,
                    float* __restrict__ out)
{
    // blockIdx.x = xy tile: xt = bx % 10 (160/TX), yt = bx / 10 (160/TY=20)
    const int xt = blockIdx.x % 10;
    const int yt = blockIdx.x / 10;
    const int x0 = xt * TX;
    const int y0 = yt * TY;
    const int z0 = blockIdx.y * TZ;
    const int b  = blockIdx.z;

    const int t    = threadIdx.x;
    const int lane = t & 31;
    const int wrp  = t >> 5;

    const float* __restrict__ w1b = w1 + (size_t)b * (size_t)DHW * 3;

    const uint32_t mbar  = (uint32_t)__cvta_generic_to_shared(s + BUF);
    const uint32_t sbase = (uint32_t)__cvta_generic_to_shared(s);

    if (t == 0) {
        asm volatile("mbarrier.init.shared.b64 [%0], 1;"
                     :: "r"(mbar) : "memory");
    }
    __syncthreads();

    if (USE_TMAP) {
        // ---- One 3D TMA tensor load: box (72 fl, 16, 24), OOB zero-fill ----
        if (t == 0) {
            asm volatile("mbarrier.arrive.expect_tx.shared.b64 _, [%0], %1;"
                         :: "r"(mbar), "n"(BUF * 4) : "memory");
            const int c0 = (z0 - HALO) * 3;
            const int c1 = y0 - HALO;
            const int c2 = b * Dd + x0 - HALO;
            asm volatile(
                "cp.async.bulk.tensor.3d.shared::cta.global.tile."
                "mbarrier::complete_tx::bytes [%0], [%1, {%2, %3, %4}], [%5];"
                :: "r"(sbase), "l"(&tmap), "r"(c0), "r"(c1), "r"(c2),
                   "r"(mbar) : "memory");
        }
    } else {
        // ---- Fallback: one 288B/240B bulk copy per (x,y) row ----
        const int zlo    = (z0 == 0) ? 0 : z0 - HALO;
        const int zhi    = (z0 + TZ + HALO > Ww) ? Ww : z0 + TZ + HALO;
        const int nbytes = (zhi - zlo) * 12;
        const int dstob  = (zlo - (z0 - HALO)) * 12;
        const int xlo = (x0 - HALO < 0) ? 0 : x0 - HALO;
        const int xhi = (x0 + TX + HALO > Dd) ? Dd : x0 + TX + HALO;
        const int ylo = (y0 - HALO < 0) ? 0 : y0 - HALO;
        const int yhi = (y0 + TY + HALO > Hh) ? Hh : y0 + TY + HALO;
        if (t == 0) {
            const unsigned total_tx =
                (unsigned)((xhi - xlo) * (yhi - ylo) * nbytes);
            asm volatile("mbarrier.arrive.expect_tx.shared.b64 _, [%0], %1;"
                         :: "r"(mbar), "r"(total_tx) : "memory");
        }
        __syncthreads();
        if (t < NROW) {
            const int hx = t >> 4;          // SY = 16
            const int hy = t & 15;
            const int cx = x0 - HALO + hx;
            const int cy = y0 - HALO + hy;
            if ((unsigned)cx < (unsigned)Dd && (unsigned)cy < (unsigned)Hh) {
                const float* src =
                    w1b + (size_t)(cx * Hh + cy) * (Ww * 3) + zlo * 3;
                asm volatile(
                    "cp.async.bulk.shared::cta.global."
                    "mbarrier::complete_tx::bytes [%0], [%1], %2, [%3];"
                    :: "r"(sbase + t * (RS * 4) + dstob), "l"(src),
                       "r"(nbytes), "r"(mbar) : "memory");
            }
        }
    }

    // ---- Compute mapping: lane = (xsub, z16); warp task = (x-pair, y) ----
    const int xsub = lane >> 4;
    const int hz   = lane & 15;
    const int z    = z0 + hz;

    // Prefetch first task's u2 while the TMA is in flight.
    int task = wrp;
    int nf;
    float nux, nuy, nuz;
    {
        const int xp = task >> 3, yi = task & 7;
        nf  = (((b * Dd + x0 + xp * 2 + xsub) * Hh + y0 + yi) * Ww + z) * 3;
        nux = __ldg(w2 + nf + 0);
        nuy = __ldg(w2 + nf + 1);
        nuz = __ldg(w2 + nf + 2);
    }

    // Wait for tile completion (acquire).
    {
        uint32_t done;
        asm volatile(
            "{\n\t.reg .pred p;\n\t"
            "mbarrier.try_wait.parity.acquire.cta.shared::cta.b64 p, [%1], 0;\n\t"
            "selp.b32 %0, 1, 0, p;\n\t}"
            : "=r"(done) : "r"(mbar) : "memory");
        while (!done) {
            asm volatile(
                "{\n\t.reg .pred p;\n\t"
                "mbarrier.try_wait.parity.acquire.cta.shared::cta.b64 p, [%1], 0, 0x989680;\n\t"
                "selp.b32 %0, 1, 0, p;\n\t}"
                : "=r"(done) : "r"(mbar) : "memory");
        }
    }

#pragma unroll 1
    for (; task < NTASK; task += NWARP) {
        const int xp = task >> 3;
        const int x  = x0 + xp * 2 + xsub;
        const int y  = y0 + (task & 7);
        const int f  = nf;
        const float u2x = nux, u2y = nuy, u2z = nuz;

        if (task + NWARP < NTASK) {      // prefetch next task's u2
            const int nt  = task + NWARP;
            const int xp2 = nt >> 3;
            nf  = (((b * Dd + x0 + xp2 * 2 + xsub) * Hh +
                    y0 + (nt & 7)) * Ww + z) * 3;
            nux = __ldg(w2 + nf + 0);
            nuy = __ldg(w2 + nf + 1);
            nuz = __ldg(w2 + nf + 2);
        }

        const float lx = fminf(fmaxf((float)x + u2x, 0.0f), (float)(Dd - 1));
        const float ly = fminf(fmaxf((float)y + u2y, 0.0f), (float)(Hh - 1));
        const float lz = fminf(fmaxf((float)z + u2z, 0.0f), (float)(Ww - 1));

        int ix0, iy0, iz0;
        float fx, fy, fz;
        fast_floor(lx, ix0, fx);
        fast_floor(ly, iy0, fy);
        fast_floor(lz, iz0, fz);
        const float wx = lx - fx, wy = ly - fy, wz = lz - fz;
        const float wx0 = 1.0f - wx, wy0 = 1.0f - wy, wz0 = 1.0f - wz;

        const int sx0 = ix0 - (x0 - HALO);
        const int sy0 = iy0 - (y0 - HALO);
        const int sz0 = iz0 - (z0 - HALO);

        float ox, oy, oz;

        const bool fast = ((unsigned)sx0 <= (unsigned)(SX - 2)) &&
                          ((unsigned)sy0 <= (unsigned)(SY - 2)) &&
                          ((unsigned)sz0 <= (unsigned)(SZ - 2));
        if (fast) {
            const int za = sz0 * 3;
            const int zb = za + 3;

            const float* p00 = s + ((sx0 << 4) + sy0) * RS;
            const float* p01 = p00 + RS;            // sy0+1
            const float* p10 = p00 + (SY * RS);     // sx0+1
            const float* p11 = p10 + RS;

            float acc[3];
#pragma unroll
            for (int c = 0; c < 3; ++c) {
                const float v00 = p00[za + c] * wz0 + p00[zb + c] * wz;
                const float v01 = p01[za + c] * wz0 + p01[zb + c] * wz;
                const float v10 = p10[za + c] * wz0 + p10[zb + c] * wz;
                const float v11 = p11[za + c] * wz0 + p11[zb + c] * wz;
                acc[c] = (v00 * wy0 + v01 * wy) * wx0 +
                         (v10 * wy0 + v11 * wy) * wx;
            }
            ox = acc[0]; oy = acc[1]; oz = acc[2];
        } else {
            // Rare slow path (~0.02% of threads): direct global gather.
            const int ix1 = min(ix0 + 1, Dd - 1);
            const int iy1 = min(iy0 + 1, Hh - 1);
            const int iz1 = min(iz0 + 1, Ww - 1);
            float a0 = 0.f, a1 = 0.f, a2 = 0.f;
#pragma unroll
            for (int cx = 0; cx < 2; ++cx) {
                const int   ix  = cx ? ix1 : ix0;
                const float wxx = cx ? wx : wx0;
#pragma unroll
                for (int cy = 0; cy < 2; ++cy) {
                    const int   iy  = cy ? iy1 : iy0;
                    const float wxy = wxx * (cy ? wy : wy0);
#pragma unroll
                    for (int cz = 0; cz < 2; ++cz) {
                        const int   iz  = cz ? iz1 : iz0;
                        const float wgt = wxy * (cz ? wz : wz0);
                        const int off = ((ix * Hh + iy) * Ww + iz) * 3;
                        a0 = fmaf(__ldg(w1b + off + 0), wgt, a0);
                        a1 = fmaf(__ldg(w1b + off + 1), wgt, a1);
                        a2 = fmaf(__ldg(w1b + off + 2), wgt, a2);
                    }
                }
            }
            ox = a0; oy = a1; oz = a2;
        }

        __stcs(out + f + 0, u2x + ox);
        __stcs(out + f + 1, u2y + oy);
        __stcs(out + f + 2, u2z + oz);
    }
}

typedef CUresult (*EncodeFn)(
    CUtensorMap*, CUtensorMapDataType, cuuint32_t, void*,
    const cuuint64_t*, const cuuint64_t*, const cuuint32_t*, const cuuint32_t*,
    CUtensorMapInterleave, CUtensorMapSwizzle, CUtensorMapL2promotion,
    CUtensorMapFloatOOBfill);

extern "C" void kernel_launch(void* const* d_in, const int* in_sizes, int n_in,
                              void* d_out, int out_size)
{
    const float* warp1 = (const float*)d_in[0];
    const float* warp2 = (const float*)d_in[1];
    float* out = (float*)d_out;

    const size_t smem_bytes = BUF * sizeof(float) + 16;  // 110,608

    // Build the 3D tensor map (cudart-only driver entry lookup).
    CUtensorMap tmap;
    bool have_tmap = false;
    {
        void* fn = nullptr;
        cudaDriverEntryPointQueryResult qr =
            cudaDriverEntryPointSymbolNotFound;
        cudaError_t e = cudaGetDriverEntryPoint(
            "cuTensorMapEncodeTiled", &fn, cudaEnableDefault, &qr);
        if (e == cudaSuccess && fn != nullptr &&
            qr == cudaDriverEntryPointSuccess) {
            cuuint64_t dims[3]    = {Ww * 3, Hh, (cuuint64_t)(2 * Dd)};
            cuuint64_t strides[2] = {Ww * 3 * 4, (cuuint64_t)Hh * Ww * 3 * 4};
            cuuint32_t box[3]     = {RS, SY, SX};
            cuuint32_t es[3]      = {1, 1, 1};
            EncodeFn enc = (EncodeFn)fn;
            CUresult r = enc(&tmap, CU_TENSOR_MAP_DATA_TYPE_FLOAT32, 3,
                             (void*)warp1, dims, strides, box, es,
                             CU_TENSOR_MAP_INTERLEAVE_NONE,
                             CU_TENSOR_MAP_SWIZZLE_NONE,
                             CU_TENSOR_MAP_L2_PROMOTION_L2_128B,
                             CU_TENSOR_MAP_FLOAT_OOB_FILL_NONE);
            have_tmap = (r == CUDA_SUCCESS);
        }
    }
    if (!have_tmap) {
        __builtin_memset(&tmap, 0, sizeof(tmap));  // unused by fallback
    }

    // 10 x-tiles * 20 y-tiles = 200 xy tiles; 10 z chunks; 2 batches.
    dim3 grid(200, Ww / TZ, 2);   // 4000 blocks

    if (have_tmap) {
        cudaFuncSetAttribute(compose_kernel<true>,
                             cudaFuncAttributeMaxDynamicSharedMemorySize,
                             (int)smem_bytes);
        compose_kernel<true><<<grid, TPB, smem_bytes>>>(tmap, warp1, warp2, out);
    } else {
        cudaFuncSetAttribute(compose_kernel<false>,
                             cudaFuncAttributeMaxDynamicSharedMemorySize,
                             (int)smem_bytes);
        compose_kernel<false><<<grid, TPB, smem_bytes>>>(tmap, warp1, warp2, out);
    }
}

// round 16
// speedup vs baseline: 1.4637x; 1.0052x over previous
#include <cuda_runtime.h>
#include <cuda.h>
#include <cstdint>

// out = u2 + trilinear(u1, grid + u2), [B=2,160,160,160,3] fp32.
// R15 structure with xy-halo 3 (z-halo 4): SY=14 restores conflict-free
// gather banking (SY*RS ≡ 16 mod 32) and cuts tile bytes 20%.
// One 3D tensor-map TMA tile load; per-row bulk-copy fallback.
// Two blocks co-reside per SM.

#define Dd 160
#define Hh 160
#define Ww 160
#define HW  (Hh * Ww)
#define DHW (Dd * HW)

#define TX 16
#define TY 8
#define TZ 16
#define XYH 3
#define ZH  4
#define SX (TX + 2 * XYH)    // 22
#define SY (TY + 2 * XYH)    // 14
#define SZ (TZ + 2 * ZH)     // 24
#define RS (SZ * 3)          // 72 floats per tile row (== 8 mod 32)
#define NROW (SX * SY)       // 308
#define BUF (NROW * RS)      // 22176 floats = 88,704 B
#define TPB 512
#define NWARP (TPB / 32)     // 16
#define NTASK ((TX / 2) * TY)// 64 warp tasks: (x-pair, y), 4 rounds exactly

#define MAGIC 12582912.0f    // 1.5 * 2^23
#define MAGIC_I 0x4B400000

extern __shared__ float s[];   // [BUF floats][mbarrier]

__device__ __forceinline__ void fast_floor(float v, int& i, float& f)
{
    const float fm = (v - 0.5f) + MAGIC;
    i = __float_as_int(fm) - MAGIC_I;
    f = fm - MAGIC;
}

template <bool USE_TMAP>
__global__ __launch_bounds__(TPB, 2)
void compose_kernel(const __grid_constant__ CUtensorMap tmap,
                    const float* __restrict__ w1,
                    const float* __restrict__ w2,
                    float* __restrict__ out)
{
    // blockIdx.x = xy tile: xt = bx % 10 (160/TX), yt = bx / 10 (160/TY=20)
    const int xt = blockIdx.x % 10;
    const int yt = blockIdx.x / 10;
    const int x0 = xt * TX;
    const int y0 = yt * TY;
    const int z0 = blockIdx.y * TZ;
    const int b  = blockIdx.z;

    const int t    = threadIdx.x;
    const int lane = t & 31;
    const int wrp  = t >> 5;

    const float* __restrict__ w1b = w1 + (size_t)b * (size_t)DHW * 3;

    const uint32_t mbar  = (uint32_t)__cvta_generic_to_shared(s + BUF);
    const uint32_t sbase = (uint32_t)__cvta_generic_to_shared(s);

    if (t == 0) {
        asm volatile("mbarrier.init.shared.b64 [%0], 1;"
                     :: "r"(mbar) : "memory");
    }
    __syncthreads();

    if (USE_TMAP) {
        // ---- One 3D TMA tensor load: box (72 fl, 14, 22), OOB zero-fill ----
        if (t == 0) {
            asm volatile("mbarrier.arrive.expect_tx.shared.b64 _, [%0], %1;"
                         :: "r"(mbar), "n"(BUF * 4) : "memory");
            const int c0 = (z0 - ZH) * 3;
            const int c1 = y0 - XYH;
            const int c2 = b * Dd + x0 - XYH;
            asm volatile(
                "cp.async.bulk.tensor.3d.shared::cta.global.tile."
                "mbarrier::complete_tx::bytes [%0], [%1, {%2, %3, %4}], [%5];"
                :: "r"(sbase), "l"(&tmap), "r"(c0), "r"(c1), "r"(c2),
                   "r"(mbar) : "memory");
        }
    } else {
        // ---- Fallback: one 288B/240B bulk copy per (x,y) row ----
        const int zlo    = (z0 == 0) ? 0 : z0 - ZH;
        const int zhi    = (z0 + TZ + ZH > Ww) ? Ww : z0 + TZ + ZH;
        const int nbytes = (zhi - zlo) * 12;
        const int dstob  = (zlo - (z0 - ZH)) * 12;
        const int xlo = (x0 - XYH < 0) ? 0 : x0 - XYH;
        const int xhi = (x0 + TX + XYH > Dd) ? Dd : x0 + TX + XYH;
        const int ylo = (y0 - XYH < 0) ? 0 : y0 - XYH;
        const int yhi = (y0 + TY + XYH > Hh) ? Hh : y0 + TY + XYH;
        if (t == 0) {
            const unsigned total_tx =
                (unsigned)((xhi - xlo) * (yhi - ylo) * nbytes);
            asm volatile("mbarrier.arrive.expect_tx.shared.b64 _, [%0], %1;"
                         :: "r"(mbar), "r"(total_tx) : "memory");
        }
        __syncthreads();
        if (t < NROW) {
            const int hx = t / SY;
            const int hy = t - hx * SY;
            const int cx = x0 - XYH + hx;
            const int cy = y0 - XYH + hy;
            if ((unsigned)cx < (unsigned)Dd && (unsigned)cy < (unsigned)Hh) {
                const float* src =
                    w1b + (size_t)(cx * Hh + cy) * (Ww * 3) + zlo * 3;
                asm volatile(
                    "cp.async.bulk.shared::cta.global."
                    "mbarrier::complete_tx::bytes [%0], [%1], %2, [%3];"
                    :: "r"(sbase + t * (RS * 4) + dstob), "l"(src),
                       "r"(nbytes), "r"(mbar) : "memory");
            }
        }
    }

    // ---- Compute mapping: lane = (xsub, z16); warp task = (x-pair, y) ----
    const int xsub = lane >> 4;
    const int hz   = lane & 15;
    const int z    = z0 + hz;

    // Prefetch first task's u2 while the TMA is in flight.
    int task = wrp;
    int nf;
    float nux, nuy, nuz;
    {
        const int xp = task >> 3, yi = task & 7;
        nf  = (((b * Dd + x0 + xp * 2 + xsub) * Hh + y0 + yi) * Ww + z) * 3;
        nux = __ldg(w2 + nf + 0);
        nuy = __ldg(w2 + nf + 1);
        nuz = __ldg(w2 + nf + 2);
    }

    // Wait for tile completion (acquire).
    {
        uint32_t done;
        asm volatile(
            "{\n\t.reg .pred p;\n\t"
            "mbarrier.try_wait.parity.acquire.cta.shared::cta.b64 p, [%1], 0;\n\t"
            "selp.b32 %0, 1, 0, p;\n\t}"
            : "=r"(done) : "r"(mbar) : "memory");
        while (!done) {
            asm volatile(
                "{\n\t.reg .pred p;\n\t"
                "mbarrier.try_wait.parity.acquire.cta.shared::cta.b64 p, [%1], 0, 0x989680;\n\t"
                "selp.b32 %0, 1, 0, p;\n\t}"
                : "=r"(done) : "r"(mbar) : "memory");
        }
    }

#pragma unroll 1
    for (; task < NTASK; task += NWARP) {
        const int xp = task >> 3;
        const int x  = x0 + xp * 2 + xsub;
        const int y  = y0 + (task & 7);
        const int f  = nf;
        const float u2x = nux, u2y = nuy, u2z = nuz;

        if (task + NWARP < NTASK) {      // prefetch next task's u2
            const int nt  = task + NWARP;
            const int xp2 = nt >> 3;
            nf  = (((b * Dd + x0 + xp2 * 2 + xsub) * Hh +
                    y0 + (nt & 7)) * Ww + z) * 3;
            nux = __ldg(w2 + nf + 0);
            nuy = __ldg(w2 + nf + 1);
            nuz = __ldg(w2 + nf + 2);
        }

        const float lx = fminf(fmaxf((float)x + u2x, 0.0f), (float)(Dd - 1));
        const float ly = fminf(fmaxf((float)y + u2y, 0.0f), (float)(Hh - 1));
        const float lz = fminf(fmaxf((float)z + u2z, 0.0f), (float)(Ww - 1));

        int ix0, iy0, iz0;
        float fx, fy, fz;
        fast_floor(lx, ix0, fx);
        fast_floor(ly, iy0, fy);
        fast_floor(lz, iz0, fz);
        const float wx = lx - fx, wy = ly - fy, wz = lz - fz;
        const float wx0 = 1.0f - wx, wy0 = 1.0f - wy, wz0 = 1.0f - wz;

        const int sx0 = ix0 - (x0 - XYH);
        const int sy0 = iy0 - (y0 - XYH);
        const int sz0 = iz0 - (z0 - ZH);

        float ox, oy, oz;

        const bool fast = ((unsigned)sx0 <= (unsigned)(SX - 2)) &&
                          ((unsigned)sy0 <= (unsigned)(SY - 2)) &&
                          ((unsigned)sz0 <= (unsigned)(SZ - 2));
        if (fast) {
            const int za = sz0 * 3;
            const int zb = za + 3;

            const float* p00 = s + (sx0 * SY + sy0) * RS;
            const float* p01 = p00 + RS;            // sy0+1
            const float* p10 = p00 + (SY * RS);     // sx0+1
            const float* p11 = p10 + RS;

            float acc[3];
#pragma unroll
            for (int c = 0; c < 3; ++c) {
                const float v00 = p00[za + c] * wz0 + p00[zb + c] * wz;
                const float v01 = p01[za + c] * wz0 + p01[zb + c] * wz;
                const float v10 = p10[za + c] * wz0 + p10[zb + c] * wz;
                const float v11 = p11[za + c] * wz0 + p11[zb + c] * wz;
                acc[c] = (v00 * wy0 + v01 * wy) * wx0 +
                         (v10 * wy0 + v11 * wy) * wx;
            }
            ox = acc[0]; oy = acc[1]; oz = acc[2];
        } else {
            // Rare slow path (~0.3% of edge lanes): direct global gather.
            const int ix1 = min(ix0 + 1, Dd - 1);
            const int iy1 = min(iy0 + 1, Hh - 1);
            const int iz1 = min(iz0 + 1, Ww - 1);
            float a0 = 0.f, a1 = 0.f, a2 = 0.f;
#pragma unroll
            for (int cx = 0; cx < 2; ++cx) {
                const int   ix  = cx ? ix1 : ix0;
                const float wxx = cx ? wx : wx0;
#pragma unroll
                for (int cy = 0; cy < 2; ++cy) {
                    const int   iy  = cy ? iy1 : iy0;
                    const float wxy = wxx * (cy ? wy : wy0);
#pragma unroll
                    for (int cz = 0; cz < 2; ++cz) {
                        const int   iz  = cz ? iz1 : iz0;
                        const float wgt = wxy * (cz ? wz : wz0);
                        const int off = ((ix * Hh + iy) * Ww + iz) * 3;
                        a0 = fmaf(__ldg(w1b + off + 0), wgt, a0);
                        a1 = fmaf(__ldg(w1b + off + 1), wgt, a1);
                        a2 = fmaf(__ldg(w1b + off + 2), wgt, a2);
                    }
                }
            }
            ox = a0; oy = a1; oz = a2;
        }

        __stcs(out + f + 0, u2x + ox);
        __stcs(out + f + 1, u2y + oy);
        __stcs(out + f + 2, u2z + oz);
    }
}

typedef CUresult (*EncodeFn)(
    CUtensorMap*, CUtensorMapDataType, cuuint32_t, void*,
    const cuuint64_t*, const cuuint64_t*, const cuuint32_t*, const cuuint32_t*,
    CUtensorMapInterleave, CUtensorMapSwizzle, CUtensorMapL2promotion,
    CUtensorMapFloatOOBfill);

extern "C" void kernel_launch(void* const* d_in, const int* in_sizes, int n_in,
                              void* d_out, int out_size)
{
    const float* warp1 = (const float*)d_in[0];
    const float* warp2 = (const float*)d_in[1];
    float* out = (float*)d_out;

    const size_t smem_bytes = BUF * sizeof(float) + 16;  // 88,720

    // Build the 3D tensor map (cudart-only driver entry lookup).
    CUtensorMap tmap;
    bool have_tmap = false;
    {
        void* fn = nullptr;
        cudaDriverEntryPointQueryResult qr =
            cudaDriverEntryPointSymbolNotFound;
        cudaError_t e = cudaGetDriverEntryPoint(
            "cuTensorMapEncodeTiled", &fn, cudaEnableDefault, &qr);
        if (e == cudaSuccess && fn != nullptr &&
            qr == cudaDriverEntryPointSuccess) {
            cuuint64_t dims[3]    = {Ww * 3, Hh, (cuuint64_t)(2 * Dd)};
            cuuint64_t strides[2] = {Ww * 3 * 4, (cuuint64_t)Hh * Ww * 3 * 4};
            cuuint32_t box[3]     = {RS, SY, SX};
            cuuint32_t es[3]      = {1, 1, 1};
            EncodeFn enc = (EncodeFn)fn;
            CUresult r = enc(&tmap, CU_TENSOR_MAP_DATA_TYPE_FLOAT32, 3,
                             (void*)warp1, dims, strides, box, es,
                             CU_TENSOR_MAP_INTERLEAVE_NONE,
                             CU_TENSOR_MAP_SWIZZLE_NONE,
                             CU_TENSOR_MAP_L2_PROMOTION_L2_128B,
                             CU_TENSOR_MAP_FLOAT_OOB_FILL_NONE);
            have_tmap = (r == CUDA_SUCCESS);
        }
    }
    if (!have_tmap) {
        __builtin_memset(&tmap, 0, sizeof(tmap));  // unused by fallback
    }

    // 10 x-tiles * 20 y-tiles = 200 xy tiles; 10 z chunks; 2 batches.
    dim3 grid(200, Ww / TZ, 2);   // 4000 blocks

    if (have_tmap) {
        cudaFuncSetAttribute(compose_kernel<true>,
                             cudaFuncAttributeMaxDynamicSharedMemorySize,
                             (int)smem_bytes);
        compose_kernel<true><<<grid, TPB, smem_bytes>>>(tmap, warp1, warp2, out);
    } else {
        cudaFuncSetAttribute(compose_kernel<false>,
                             cudaFuncAttributeMaxDynamicSharedMemorySize,
                             (int)smem_bytes);
        compose_kernel<false><<<grid, TPB, smem_bytes>>>(tmap, warp1, warp2, out);
    }
}